// round 14
// baseline (speedup 1.0000x reference)
#include <cuda_runtime.h>
#include <cuda_bf16.h>
#include <mma.h>
#include <math.h>
#include <stdint.h>

using namespace nvcuda;

// ===== Problem constants (fixed shapes) =====
#define NB    4
#define LSEQ  8192
#define MTOT  (NB*LSEQ)   // 32768 rows
#define CDIM  256
#define HDIM  512
#define NHEAD 8
#define DHEAD 32

// ===== Scratch (no cudaMalloc; __device__ globals) =====
__device__ __align__(128) float g_qraw [(size_t)MTOT*CDIM]; // x@Wq^T (pre-ELU)
__device__ __align__(128) float g_kraw [(size_t)MTOT*CDIM]; // src@Wk^T (pre-ELU)
__device__ __align__(128) float g_vproj[(size_t)MTOT*CDIM];
__device__ __align__(128) float g_msgm [(size_t)MTOT*CDIM];
__device__ __align__(128) float g_h2   [(size_t)MTOT*CDIM];
__device__ float g_KV  [NB*NHEAD*DHEAD*DHEAD]; // includes 1/S
__device__ float g_Ksum[NB*NHEAD*DHEAD];
// bf16 split-2 "cat3" operands: X-side = [hi | lo | hi], W-side = [hi | hi | lo]
// single GEMM over 3K computes hi*hi + lo*hi + hi*lo  (only lo*lo ~2^-16 dropped)
__device__ __align__(128) __nv_bfloat16 g_xcat  [(size_t)MTOT*3*CDIM]; // x       [M,768]
__device__ __align__(128) __nv_bfloat16 g_scat  [(size_t)MTOT*3*CDIM]; // source  [M,768]
__device__ __align__(128) __nv_bfloat16 g_mcat  [(size_t)MTOT*3*CDIM]; // message [M,768]
__device__ __align__(128) __nv_bfloat16 g_mlncat[(size_t)MTOT*3*CDIM]; // LN1 msg [M,768]
__device__ __align__(128) __nv_bfloat16 g_h1cat [(size_t)MTOT*3*HDIM]; // relu h1 [M,1536]
__device__ __align__(128) __nv_bfloat16 g_wqcat[(size_t)CDIM*3*CDIM];
__device__ __align__(128) __nv_bfloat16 g_wkcat[(size_t)CDIM*3*CDIM];
__device__ __align__(128) __nv_bfloat16 g_wvcat[(size_t)CDIM*3*CDIM];
__device__ __align__(128) __nv_bfloat16 g_wmcat[(size_t)CDIM*3*CDIM];
__device__ __align__(128) __nv_bfloat16 g_w1cat[(size_t)HDIM*3*HDIM];
__device__ __align__(128) __nv_bfloat16 g_w2cat[(size_t)CDIM*3*HDIM];

__device__ __forceinline__ float elu1(float v) {
    return v > 0.f ? v + 1.f : expf(v); // elu(v)+1
}

// ===== helpers =====
__device__ __forceinline__ uint32_t smem_u32(const void* p) {
    uint32_t a;
    asm("{ .reg .u64 t; cvta.to.shared.u64 t, %1; cvt.u32.u64 %0, t; }" : "=r"(a) : "l"(p));
    return a;
}
__device__ __forceinline__ void cpasync16(uint32_t s, const void* g) {
    asm volatile("cp.async.cg.shared.global [%0], [%1], 16;" :: "r"(s), "l"(g) : "memory");
}
// bf16 hi/lo split
__device__ __forceinline__ void split_bf16(float v, __nv_bfloat16& h, __nv_bfloat16& l) {
    h = __float2bfloat16(v);
    l = __float2bfloat16(v - __bfloat162float(h));
}

// ===== WMMA GEMM:  Y[M,NN] = A[M,K3] @ Wcat[NN,K3]^T =====
// CTA 128x128, 128 threads, 4 warps (2x2), warp tile 64x64 (best mma:ldsm = 2.0;
// R12 showed 8-warp/64x32 raises LDSM traffic 1.5x and regresses).
// BK=32, padded rows (ld=40 bf16 = 80B, conflict-free ldmatrix).
// 3-stage cp.async ring (wait_group 1 steady-state) in 60KB DYNAMIC smem ->
// absorbs L2 latency (234-262cy) and allows 3 CTAs/SM.
// SPLIT: A-operand composed on the fly from two 768-wide sources
//   (x cat3 | msg_ln cat3) -> the 1536-wide concat is never materialized.
// CAT3 epilogue: act + hi/lo split -> [hi|lo|hi] via per-warp smem staging.
#define BKW 32
#define LDP 40            // row ld in bf16 (80B)
#define STG_B 20480       // bytes per stage (A 10240 + B 10240)
#define GEMM_DSMEM (3 * STG_B)

#define ACT_NONE 0
#define ACT_RELU 2

template<int ACT, bool CAT3, bool SPLIT, int NN, int K3>
__device__ __forceinline__ void wmma_body(const __nv_bfloat16* __restrict__ X,
                                          const __nv_bfloat16* __restrict__ X2,
                                          const __nv_bfloat16* __restrict__ Wc,
                                          float* __restrict__ fout,
                                          __nv_bfloat16* __restrict__ bout) {
    extern __shared__ __align__(128) char dsm[];

    const int tid  = threadIdx.x;     // 0..127
    const int wid  = tid >> 5;        // 0..3
    const int lane = tid & 31;
    const int bm   = blockIdx.y * 128;
    const int bn   = blockIdx.x * 128;
    const int wm   = (wid & 1) * 64;  // warp grid 2x2, tile 64x64
    const int wn   = (wid >> 1) * 64;
    constexpr int NC = K3 / BKW;

    auto aP = [&](int st, int r) -> char* { return dsm + st * STG_B + r * 80; };
    auto bP = [&](int st, int r) -> char* { return dsm + st * STG_B + 10240 + r * 80; };

    auto load_stage = [&](int c, int st) {
        // A source: plain (stride K3) or composed from X / X2 (both 768-wide)
        const __nv_bfloat16* asrc;
        int acol, astride;
        if (SPLIT) {
            const int seg = c >> 4;           // 512-col segment of virtual concat
            const int w   = c & 15;           // chunk within segment
            asrc    = (w < 8) ? X : X2;       // x-half vs msg_ln-half
            acol    = seg * 256 + (w & 7) * 32;
            astride = 768;
        } else {
            asrc = X; acol = c * BKW; astride = K3;
        }
        #pragma unroll
        for (int i = tid; i < 512; i += 128) {   // 128 rows x 4 chunks of 16B
            const int r  = i >> 2;
            const int ch = i & 3;
            cpasync16(smem_u32(aP(st, r) + ch * 16),
                      asrc + (size_t)(bm + r) * astride + acol + ch * 8);
            cpasync16(smem_u32(bP(st, r) + ch * 16),
                      Wc + (size_t)(bn + r) * K3 + c * BKW + ch * 8);
        }
        asm volatile("cp.async.commit_group;" ::: "memory");
    };

    wmma::fragment<wmma::accumulator, 16, 16, 16, float> acc[4][4];
    #pragma unroll
    for (int i = 0; i < 4; ++i)
        #pragma unroll
        for (int j = 0; j < 4; ++j) wmma::fill_fragment(acc[i][j], 0.0f);

    load_stage(0, 0);
    load_stage(1, 1);

    for (int c = 0; c < NC; ++c) {
        if (c + 1 < NC) asm volatile("cp.async.wait_group 1;" ::: "memory");
        else            asm volatile("cp.async.wait_group 0;" ::: "memory");
        __syncthreads();                  // chunk c ready + prior compute done
        if (c + 2 < NC) load_stage(c + 2, (c + 2) % 3);
        const int st = c % 3;

        #pragma unroll
        for (int kk = 0; kk < BKW / 16; ++kk) {
            wmma::fragment<wmma::matrix_a, 16, 16, 16, __nv_bfloat16, wmma::row_major> af[4];
            wmma::fragment<wmma::matrix_b, 16, 16, 16, __nv_bfloat16, wmma::col_major> bf[4];
            #pragma unroll
            for (int i = 0; i < 4; ++i)
                wmma::load_matrix_sync(af[i],
                    (const __nv_bfloat16*)aP(st, wm + i * 16) + kk * 16, LDP);
            #pragma unroll
            for (int j = 0; j < 4; ++j)
                wmma::load_matrix_sync(bf[j],
                    (const __nv_bfloat16*)bP(st, wn + j * 16) + kk * 16, LDP);
            #pragma unroll
            for (int i = 0; i < 4; ++i)
                #pragma unroll
                for (int j = 0; j < 4; ++j)
                    wmma::mma_sync(acc[i][j], af[i], bf[j], acc[i][j]);
        }
    }

    if (!CAT3) {
        #pragma unroll
        for (int i = 0; i < 4; ++i)
            #pragma unroll
            for (int j = 0; j < 4; ++j)
                wmma::store_matrix_sync(
                    &fout[(size_t)(bm + wm + i * 16) * NN + bn + wn + j * 16],
                    acc[i][j], NN, wmma::mem_row_major);
    } else {
        // per-warp 16x16 float staging overlaid on stage memory (mainloop done)
        __syncthreads();
        float* stg = reinterpret_cast<float*>(dsm) + wid * 256;
        const int er = lane >> 1;          // staging row this lane reads
        const int ec = (lane & 1) * 8;     // 8 consecutive cols
        #pragma unroll
        for (int i = 0; i < 4; ++i) {
            #pragma unroll
            for (int j = 0; j < 4; ++j) {
                wmma::store_matrix_sync(stg, acc[i][j], 16, wmma::mem_row_major);
                __syncwarp();
                const int mrow = bm + wm + i * 16 + er;
                const int col  = bn + wn + j * 16 + ec;
                __nv_bfloat16* o = bout + (size_t)mrow * (3 * NN) + col;
                #pragma unroll
                for (int t = 0; t < 8; t += 2) {
                    float v0 = stg[er * 16 + ec + t];
                    float v1 = stg[er * 16 + ec + t + 1];
                    if (ACT == ACT_RELU) {
                        v0 = v0 > 0.f ? v0 : 0.f;
                        v1 = v1 > 0.f ? v1 : 0.f;
                    }
                    __nv_bfloat16 h0, h1, l0, l1;
                    split_bf16(v0, h0, l0); split_bf16(v1, h1, l1);
                    __nv_bfloat162 hh, ll;
                    hh.x = h0; hh.y = h1; ll.x = l0; ll.y = l1;
                    *(__nv_bfloat162*)&o[t]          = hh;   // seg0: hi
                    *(__nv_bfloat162*)&o[NN + t]     = ll;   // seg1: lo
                    *(__nv_bfloat162*)&o[2 * NN + t] = hh;   // seg2: hi
                }
                __syncwarp();
            }
        }
    }
}

__global__ void __launch_bounds__(128) k_wq() {
    wmma_body<ACT_NONE, false, false, 256, 768>(g_xcat, nullptr, g_wqcat, g_qraw, nullptr);
}
__global__ void __launch_bounds__(128) k_wk() {
    wmma_body<ACT_NONE, false, false, 256, 768>(g_scat, nullptr, g_wkcat, g_kraw, nullptr);
}
__global__ void __launch_bounds__(128) k_wv() {
    wmma_body<ACT_NONE, false, false, 256, 768>(g_scat, nullptr, g_wvcat, g_vproj, nullptr);
}
__global__ void __launch_bounds__(128) k_wm() {
    wmma_body<ACT_NONE, false, false, 256, 768>(g_mcat, nullptr, g_wmcat, g_msgm, nullptr);
}
__global__ void __launch_bounds__(128) k_w1() {
    // h1cat = cat3(relu([x|msgln] W1^T)); concat composed in the loader
    wmma_body<ACT_RELU, true, true, 512, 1536>(g_xcat, g_mlncat, g_w1cat, nullptr, g_h1cat);
}
__global__ void __launch_bounds__(128) k_w2() {
    wmma_body<ACT_NONE, false, false, 256, 1536>(g_h1cat, nullptr, g_w2cat, g_h2, nullptr);
}

// ===== Weight conversion (ALL 6 matrices in ONE launch; grid.y selects) =====
// Wcat[n, 3K] = [hi | hi | lo]. Output globals bound in device code —
// passing a __device__ global as a host-side arg hits the host shadow symbol
// (ATS swallows the writes silently): the R9/R10 bug. Never do that.
__device__ __forceinline__ void conv_w_elem(const float* __restrict__ W,
                                            __nv_bfloat16* __restrict__ out,
                                            int K, size_t i) {
    const int kh = K >> 1;
    const size_t row = i / kh;
    const int p = (int)(i % kh) * 2;
    const float2 w = *(const float2*)&W[row * K + p];
    __nv_bfloat16 h0, h1, l0, l1;
    split_bf16(w.x, h0, l0); split_bf16(w.y, h1, l1);
    __nv_bfloat162 hh, ll; hh.x = h0; hh.y = h1; ll.x = l0; ll.y = l1;
    __nv_bfloat16* o = out + row * (size_t)(3 * K);
    *(__nv_bfloat162*)&o[p]         = hh;
    *(__nv_bfloat162*)&o[K + p]     = hh;
    *(__nv_bfloat162*)&o[2 * K + p] = ll;
}
__global__ void k_conv_w_all(const float* Wq, const float* Wk, const float* Wv,
                             const float* Wm, const float* W1, const float* W2) {
    const size_t i = (size_t)blockIdx.x * 256 + threadIdx.x;
    switch (blockIdx.y) {
        case 0: if (i < CDIM*CDIM/2) conv_w_elem(Wq, g_wqcat, CDIM, i); break;
        case 1: if (i < CDIM*CDIM/2) conv_w_elem(Wk, g_wkcat, CDIM, i); break;
        case 2: if (i < CDIM*CDIM/2) conv_w_elem(Wv, g_wvcat, CDIM, i); break;
        case 3: if (i < CDIM*CDIM/2) conv_w_elem(Wm, g_wmcat, CDIM, i); break;
        case 4: if (i < HDIM*HDIM/2) conv_w_elem(W1, g_w1cat, HDIM, i); break;
        default: if (i < CDIM*HDIM/2) conv_w_elem(W2, g_w2cat, HDIM, i); break;
    }
}

// x: xcat[m,768] = [hi|lo|hi]  (g1in eliminated — k_w1 composes the concat)
__global__ void k_conv_x(const float* __restrict__ X) {
    const size_t i = (size_t)blockIdx.x * 256 + threadIdx.x; // over MTOT*128
    const size_t m = i >> 7;
    const int p = (int)(i & 127) * 2;
    const float2 xv = *(const float2*)&X[m * CDIM + p];
    __nv_bfloat16 h0, h1, l0, l1;
    split_bf16(xv.x, h0, l0); split_bf16(xv.y, h1, l1);
    __nv_bfloat162 hh, ll; hh.x = h0; hh.y = h1; ll.x = l0; ll.y = l1;
    __nv_bfloat16* xc = g_xcat + m * 768;
    *(__nv_bfloat162*)&xc[p]       = hh;
    *(__nv_bfloat162*)&xc[256 + p] = ll;
    *(__nv_bfloat162*)&xc[512 + p] = hh;
}
// source: scat[m,768] = [hi|lo|hi]
__global__ void k_conv_s(const float* __restrict__ S) {
    const size_t i = (size_t)blockIdx.x * 256 + threadIdx.x;
    const size_t m = i >> 7;
    const int p = (int)(i & 127) * 2;
    const float2 sv = *(const float2*)&S[m * CDIM + p];
    __nv_bfloat16 h0, h1, l0, l1;
    split_bf16(sv.x, h0, l0); split_bf16(sv.y, h1, l1);
    __nv_bfloat162 hh, ll; hh.x = h0; hh.y = h1; ll.x = l0; ll.y = l1;
    __nv_bfloat16* sc = g_scat + m * 768;
    *(__nv_bfloat162*)&sc[p]       = hh;
    *(__nv_bfloat162*)&sc[256 + p] = ll;
    *(__nv_bfloat162*)&sc[512 + p] = hh;
}

// ===== zero KV/Ksum accumulators =====
__global__ void zero_kv_kernel() {
    const int i = blockIdx.x * 256 + threadIdx.x;
    if (i < NB*NHEAD*DHEAD*DHEAD) g_KV[i] = 0.f;
    if (i < NB*NHEAD*DHEAD)       g_Ksum[i] = 0.f;
}

// ===== KV = sum_s elu1(K)[s,h,d] * v[s,h,v] / S ;  Ksum = sum_s elu1(K) =====
__global__ void __launch_bounds__(256) kv_reduce_kernel() {
    const int split = blockIdx.x, h = blockIdx.y, n = blockIdx.z;
    __shared__ __align__(16) float sk[64][32];
    __shared__ __align__(16) float sv[64][32];
    const int tid = threadIdx.x;
    const int v  = tid & 31;
    const int d0 = tid >> 5;

    float kv[4] = {0.f, 0.f, 0.f, 0.f};
    float ks[4] = {0.f, 0.f, 0.f, 0.f};

    const int ROWS = LSEQ / 16;
    const int srow0 = n * LSEQ + split * ROWS;

    for (int s0 = 0; s0 < ROWS; s0 += 64) {
        __syncthreads();
        #pragma unroll
        for (int t = 0; t < 2; ++t) {
            const int i = tid + t * 256;
            const int r = i >> 3, c = (i & 7) * 4;
            const size_t gidx = (size_t)(srow0 + s0 + r) * CDIM + h * DHEAD + c;
            float4 kf = *(const float4*)&g_kraw[gidx];
            kf.x = elu1(kf.x); kf.y = elu1(kf.y);
            kf.z = elu1(kf.z); kf.w = elu1(kf.w);
            *(float4*)&sk[r][c] = kf;
            *(float4*)&sv[r][c] = *(const float4*)&g_vproj[gidx];
        }
        __syncthreads();
        for (int r = 0; r < 64; ++r) {
            const float vv = sv[r][v];
            #pragma unroll
            for (int q = 0; q < 4; ++q) {
                const float kd = sk[r][d0 + 8*q];
                kv[q] += kd * vv;
                ks[q] += kd;
            }
        }
    }
    #pragma unroll
    for (int q = 0; q < 4; ++q) {
        const int d = d0 + 8*q;
        atomicAdd(&g_KV[(((size_t)n*NHEAD + h)*DHEAD + d)*DHEAD + v],
                  kv[q] * (1.0f / (float)LSEQ));
        if (v == 0)
            atomicAdd(&g_Ksum[((size_t)n*NHEAD + h)*DHEAD + d], ks[q]);
    }
}

// ===== attention: Q=elu1(qraw); msg -> cat3 bf16 directly =====
__global__ void __launch_bounds__(256) attn_kernel() {
    const int n = blockIdx.y;
    __shared__ __align__(16) float sKV[NHEAD*DHEAD*DHEAD];
    __shared__ float sKs[NHEAD*DHEAD];
    const int tid = threadIdx.x;

    for (int i = tid; i < NHEAD*DHEAD*DHEAD/4; i += 256)
        *(float4*)&sKV[i*4] = *(const float4*)&g_KV[(size_t)n*NHEAD*DHEAD*DHEAD + i*4];
    sKs[tid] = g_Ksum[n*NHEAD*DHEAD + tid];
    __syncthreads();

    const size_t row = (size_t)n * LSEQ + (size_t)blockIdx.x * 256 + tid;
    const float* qrow = g_qraw + row * CDIM;
    __nv_bfloat16* mr = g_mcat + row * 768;

    for (int h = 0; h < NHEAD; ++h) {
        float Q[DHEAD];
        #pragma unroll
        for (int i = 0; i < 8; ++i)
            *(float4*)&Q[i*4] = *(const float4*)&qrow[h*DHEAD + i*4];
        #pragma unroll
        for (int d = 0; d < DHEAD; ++d) Q[d] = elu1(Q[d]);

        float zden = 1e-6f;
        #pragma unroll
        for (int d = 0; d < DHEAD; ++d) zden += Q[d] * sKs[h*DHEAD + d];
        const float z = (float)LSEQ / zden;

        #pragma unroll
        for (int v4 = 0; v4 < 8; ++v4) {
            float ax = 0.f, ay = 0.f, az = 0.f, aw = 0.f;
            #pragma unroll
            for (int d = 0; d < DHEAD; ++d) {
                const float4 kv = *(const float4*)&sKV[(h*DHEAD + d)*DHEAD + v4*4];
                const float qd = Q[d];
                ax += qd * kv.x; ay += qd * kv.y; az += qd * kv.z; aw += qd * kv.w;
            }
            const float o0 = ax*z, o1 = ay*z, o2 = az*z, o3 = aw*z;
            __nv_bfloat16 h0,h1,h2,h3,l0,l1,l2,l3;
            split_bf16(o0,h0,l0); split_bf16(o1,h1,l1);
            split_bf16(o2,h2,l2); split_bf16(o3,h3,l3);
            __nv_bfloat162 ha,hb,la,lb;
            ha.x=h0; ha.y=h1; hb.x=h2; hb.y=h3;
            la.x=l0; la.y=l1; lb.x=l2; lb.y=l3;
            const int col = h*DHEAD + v4*4;
            *(__nv_bfloat162*)&mr[col]           = ha;
            *(__nv_bfloat162*)&mr[col + 2]       = hb;
            *(__nv_bfloat162*)&mr[256 + col]     = la;
            *(__nv_bfloat162*)&mr[256 + col + 2] = lb;
            *(__nv_bfloat162*)&mr[512 + col]     = ha;
            *(__nv_bfloat162*)&mr[512 + col + 2] = hb;
        }
    }
}

// ===== LN1: LayerNorm(g_msgm) -> g_mlncat [hi|lo|hi] (768-wide) =====
__global__ void __launch_bounds__(256) k_ln1(const float* __restrict__ gamma,
                                             const float* __restrict__ beta) {
    const int w = threadIdx.x >> 5, lane = threadIdx.x & 31;
    const size_t row = (size_t)blockIdx.x * 8 + w;
    const float* p = g_msgm + row * CDIM;

    const float4 v0 = *(const float4*)&p[lane*4];
    const float4 v1 = *(const float4*)&p[128 + lane*4];

    float s  = v0.x + v0.y + v0.z + v0.w + v1.x + v1.y + v1.z + v1.w;
    float s2 = v0.x*v0.x + v0.y*v0.y + v0.z*v0.z + v0.w*v0.w
             + v1.x*v1.x + v1.y*v1.y + v1.z*v1.z + v1.w*v1.w;
    #pragma unroll
    for (int o = 16; o; o >>= 1) {
        s  += __shfl_xor_sync(0xFFFFFFFFu, s,  o);
        s2 += __shfl_xor_sync(0xFFFFFFFFu, s2, o);
    }
    const float mu  = s * (1.f / 256.f);
    const float var = s2 * (1.f / 256.f) - mu * mu;
    const float rs  = rsqrtf(var + 1e-5f);

    __nv_bfloat16* ml = g_mlncat + row * 768;
    #pragma unroll
    for (int half = 0; half < 2; ++half) {
        const float4 v = half ? v1 : v0;
        const int k = half * 128 + lane * 4;
        const float4 gm = *(const float4*)&gamma[k];
        const float4 bt = *(const float4*)&beta[k];
        const float o0 = (v.x - mu)*rs*gm.x + bt.x;
        const float o1 = (v.y - mu)*rs*gm.y + bt.y;
        const float o2 = (v.z - mu)*rs*gm.z + bt.z;
        const float o3 = (v.w - mu)*rs*gm.w + bt.w;
        __nv_bfloat16 h0,h1,h2,h3,l0,l1,l2,l3;
        split_bf16(o0,h0,l0); split_bf16(o1,h1,l1);
        split_bf16(o2,h2,l2); split_bf16(o3,h3,l3);
        __nv_bfloat162 ha,hb,la,lb;
        ha.x=h0; ha.y=h1; hb.x=h2; hb.y=h3;
        la.x=l0; la.y=l1; lb.x=l2; lb.y=l3;
        *(__nv_bfloat162*)&ml[k]            = ha;
        *(__nv_bfloat162*)&ml[k + 2]        = hb;
        *(__nv_bfloat162*)&ml[256 + k]      = la;
        *(__nv_bfloat162*)&ml[256 + k + 2]  = lb;
        *(__nv_bfloat162*)&ml[512 + k]      = ha;
        *(__nv_bfloat162*)&ml[512 + k + 2]  = hb;
    }
}

// ===== LN2 + residual: out = x + LN(g_h2) =====
__global__ void __launch_bounds__(256) k_ln2(const float* __restrict__ gamma,
                                             const float* __restrict__ beta,
                                             const float* __restrict__ xres,
                                             float* __restrict__ out) {
    const int w = threadIdx.x >> 5, lane = threadIdx.x & 31;
    const size_t row = (size_t)blockIdx.x * 8 + w;
    const float* p = g_h2 + row * CDIM;

    const float4 v0 = *(const float4*)&p[lane*4];
    const float4 v1 = *(const float4*)&p[128 + lane*4];

    float s  = v0.x + v0.y + v0.z + v0.w + v1.x + v1.y + v1.z + v1.w;
    float s2 = v0.x*v0.x + v0.y*v0.y + v0.z*v0.z + v0.w*v0.w
             + v1.x*v1.x + v1.y*v1.y + v1.z*v1.z + v1.w*v1.w;
    #pragma unroll
    for (int o = 16; o; o >>= 1) {
        s  += __shfl_xor_sync(0xFFFFFFFFu, s,  o);
        s2 += __shfl_xor_sync(0xFFFFFFFFu, s2, o);
    }
    const float mu  = s * (1.f / 256.f);
    const float var = s2 * (1.f / 256.f) - mu * mu;
    const float rs  = rsqrtf(var + 1e-5f);

    const float4 gm0 = *(const float4*)&gamma[lane*4];
    const float4 gm1 = *(const float4*)&gamma[128 + lane*4];
    const float4 bt0 = *(const float4*)&beta[lane*4];
    const float4 bt1 = *(const float4*)&beta[128 + lane*4];
    const float4 x0  = *(const float4*)&xres[row*CDIM + lane*4];
    const float4 x1  = *(const float4*)&xres[row*CDIM + 128 + lane*4];

    float4 o0, o1;
    o0.x = x0.x + (v0.x - mu)*rs*gm0.x + bt0.x;  o0.y = x0.y + (v0.y - mu)*rs*gm0.y + bt0.y;
    o0.z = x0.z + (v0.z - mu)*rs*gm0.z + bt0.z;  o0.w = x0.w + (v0.w - mu)*rs*gm0.w + bt0.w;
    o1.x = x1.x + (v1.x - mu)*rs*gm1.x + bt1.x;  o1.y = x1.y + (v1.y - mu)*rs*gm1.y + bt1.y;
    o1.z = x1.z + (v1.z - mu)*rs*gm1.z + bt1.z;  o1.w = x1.w + (v1.w - mu)*rs*gm1.w + bt1.w;

    *(float4*)&out[row*CDIM + lane*4]       = o0;
    *(float4*)&out[row*CDIM + 128 + lane*4] = o1;
}

// ===== Launch =====
extern "C" void kernel_launch(void* const* d_in, const int* in_sizes, int n_in,
                              void* d_out, int out_size) {
    const float* x    = (const float*)d_in[0];
    const float* src  = (const float*)d_in[1];
    const float* Wq   = (const float*)d_in[2];
    const float* Wk   = (const float*)d_in[3];
    const float* Wv   = (const float*)d_in[4];
    const float* Wm   = (const float*)d_in[5];
    const float* ln1g = (const float*)d_in[6];
    const float* ln1b = (const float*)d_in[7];
    const float* W1   = (const float*)d_in[8];
    const float* W2   = (const float*)d_in[9];
    const float* ln2g = (const float*)d_in[10];
    const float* ln2b = (const float*)d_in[11];
    float* out = (float*)d_out;

    // opt-in >48KB dynamic smem for the GEMMs (idempotent; host API, no alloc)
    cudaFuncSetAttribute(k_wq, cudaFuncAttributeMaxDynamicSharedMemorySize, GEMM_DSMEM);
    cudaFuncSetAttribute(k_wk, cudaFuncAttributeMaxDynamicSharedMemorySize, GEMM_DSMEM);
    cudaFuncSetAttribute(k_wv, cudaFuncAttributeMaxDynamicSharedMemorySize, GEMM_DSMEM);
    cudaFuncSetAttribute(k_wm, cudaFuncAttributeMaxDynamicSharedMemorySize, GEMM_DSMEM);
    cudaFuncSetAttribute(k_w1, cudaFuncAttributeMaxDynamicSharedMemorySize, GEMM_DSMEM);
    cudaFuncSetAttribute(k_w2, cudaFuncAttributeMaxDynamicSharedMemorySize, GEMM_DSMEM);

    const dim3 blk(128);
    const dim3 gq(256 / 128, MTOT / 128);   // (2, 256)
    const dim3 g1(512 / 128, MTOT / 128);   // (4, 256)

    // GEMMs at launch positions 4-6 so ncu (-s/-c bounded) lands on one.
    k_conv_x<<<(size_t)MTOT*128/256, 256>>>(x);                       // 1
    k_conv_w_all<<<dim3(512, 6), 256>>>(Wq, Wk, Wv, Wm, W1, W2);      // 2
    k_conv_s<<<(size_t)MTOT*128/256, 256>>>(src);                     // 3
    k_wq<<<gq, blk, GEMM_DSMEM>>>();                                  // 4 <- profiled
    k_wk<<<gq, blk, GEMM_DSMEM>>>();                                  // 5
    k_wv<<<gq, blk, GEMM_DSMEM>>>();                                  // 6
    zero_kv_kernel<<<128, 256>>>();
    kv_reduce_kernel<<<dim3(16, NHEAD, NB), 256>>>();   // elu applied on K here
    attn_kernel<<<dim3(LSEQ / 256, NB), 256>>>();       // elu on Q; msg -> g_mcat
    k_wm<<<gq, blk, GEMM_DSMEM>>>();        // msgm = msg Wm^T
    k_ln1<<<MTOT / 8, 256>>>(ln1g, ln1b);   // msg_ln -> g_mlncat (cat3)
    k_w1<<<g1, blk, GEMM_DSMEM>>>();        // h1cat = cat3(relu([x|msgln] W1^T))
    k_w2<<<gq, blk, GEMM_DSMEM>>>();        // h2 = relu(h1) W2^T
    k_ln2<<<MTOT / 8, 256>>>(ln2g, ln2b, x, out);
}

// round 15
// speedup vs baseline: 1.0368x; 1.0368x over previous
#include <cuda_runtime.h>
#include <cuda_bf16.h>
#include <mma.h>
#include <math.h>
#include <stdint.h>

using namespace nvcuda;

// ===== Problem constants (fixed shapes) =====
#define NB    4
#define LSEQ  8192
#define MTOT  (NB*LSEQ)   // 32768 rows
#define CDIM  256
#define HDIM  512
#define NHEAD 8
#define DHEAD 32

// ===== Scratch (no cudaMalloc; __device__ globals) =====
__device__ __align__(128) float g_qraw [(size_t)MTOT*CDIM]; // x@Wq^T (pre-ELU)
__device__ __align__(128) float g_kraw [(size_t)MTOT*CDIM]; // src@Wk^T (pre-ELU)
__device__ __align__(128) float g_vproj[(size_t)MTOT*CDIM];
__device__ __align__(128) float g_msgm [(size_t)MTOT*CDIM];
__device__ __align__(128) float g_h2   [(size_t)MTOT*CDIM];
__device__ float g_KV  [NB*NHEAD*DHEAD*DHEAD]; // includes 1/S
__device__ float g_Ksum[NB*NHEAD*DHEAD];
// bf16 split-2 "cat3" operands: X-side = [hi | lo | hi], W-side = [hi | hi | lo]
// single GEMM over 3K computes hi*hi + lo*hi + hi*lo  (only lo*lo ~2^-16 dropped)
__device__ __align__(128) __nv_bfloat16 g_xcat  [(size_t)MTOT*3*CDIM]; // x       [M,768]
__device__ __align__(128) __nv_bfloat16 g_scat  [(size_t)MTOT*3*CDIM]; // source  [M,768]
__device__ __align__(128) __nv_bfloat16 g_mcat  [(size_t)MTOT*3*CDIM]; // message [M,768]
__device__ __align__(128) __nv_bfloat16 g_mlncat[(size_t)MTOT*3*CDIM]; // LN1 msg [M,768]
__device__ __align__(128) __nv_bfloat16 g_h1cat [(size_t)MTOT*3*HDIM]; // relu h1 [M,1536]
__device__ __align__(128) __nv_bfloat16 g_wqcat[(size_t)CDIM*3*CDIM];
__device__ __align__(128) __nv_bfloat16 g_wkcat[(size_t)CDIM*3*CDIM];
__device__ __align__(128) __nv_bfloat16 g_wvcat[(size_t)CDIM*3*CDIM];
__device__ __align__(128) __nv_bfloat16 g_wmcat[(size_t)CDIM*3*CDIM];
__device__ __align__(128) __nv_bfloat16 g_w1cat[(size_t)HDIM*3*HDIM];
__device__ __align__(128) __nv_bfloat16 g_w2cat[(size_t)CDIM*3*HDIM];

__device__ __forceinline__ float elu1(float v) {
    return v > 0.f ? v + 1.f : expf(v); // elu(v)+1
}

// ===== helpers =====
__device__ __forceinline__ uint32_t smem_u32(const void* p) {
    uint32_t a;
    asm("{ .reg .u64 t; cvta.to.shared.u64 t, %1; cvt.u32.u64 %0, t; }" : "=r"(a) : "l"(p));
    return a;
}
__device__ __forceinline__ void cpasync16(uint32_t s, const void* g) {
    asm volatile("cp.async.cg.shared.global [%0], [%1], 16;" :: "r"(s), "l"(g) : "memory");
}
// bf16 hi/lo split
__device__ __forceinline__ void split_bf16(float v, __nv_bfloat16& h, __nv_bfloat16& l) {
    h = __float2bfloat16(v);
    l = __float2bfloat16(v - __bfloat162float(h));
}

// ===== WMMA GEMM:  Y[M,NN] = A[M,K3] @ Wcat[NN,K3]^T =====
// CTA 128x128, 128 threads, 4 warps (2x2), warp tile 64x64 (best mma:ldsm = 2.0;
// R12: 8-warp/64x32 raises LDSM 1.5x and regresses).
// 2-stage static-48KB cp.async ring (R14: 3-stage was neutral-negative — regs,
// not smem, cap occupancy at 3 CTAs/SM).
// R14 ncu: tensor 35.5%, DRAM 11% -> GEMMs are WAVE-TAIL bound (512 CTAs vs
// 444 capacity = 1.15 waves). Fix = merge QKV into one launch (below).
// SPLIT: A composed on the fly from two 768-wide sources ([x|msg_ln] never
// materialized). CAT3 epilogue: act + hi/lo split -> [hi|lo|hi].
#define BKW 32
#define LDP 40   // BKW + 8 pad; 80B rows, multiple of 16B

#define ACT_NONE 0
#define ACT_RELU 2

template<int ACT, bool CAT3, bool SPLIT, int NN, int K3>
__device__ __forceinline__ void wmma_body(const __nv_bfloat16* __restrict__ X,
                                          const __nv_bfloat16* __restrict__ X2,
                                          const __nv_bfloat16* __restrict__ Wc,
                                          float* __restrict__ fout,
                                          __nv_bfloat16* __restrict__ bout) {
    __shared__ __align__(128) __nv_bfloat16 As[2][128][LDP]; // 2*10240B
    __shared__ __align__(128) __nv_bfloat16 Bs[2][128][LDP];

    const int tid  = threadIdx.x;     // 0..127
    const int wid  = tid >> 5;        // 0..3
    const int lane = tid & 31;
    const int bm   = blockIdx.y * 128;
    const int bn   = blockIdx.x * 128;
    const int wm   = (wid & 1) * 64;  // warp grid 2x2, tile 64x64
    const int wn   = (wid >> 1) * 64;
    constexpr int NC = K3 / BKW;

    auto load_stage = [&](int c, int st) {
        const __nv_bfloat16* asrc;
        int acol, astride;
        if (SPLIT) {                          // virtual [x | msg_ln] concat
            const int seg = c >> 4;           // 512-col segment
            const int w   = c & 15;           // chunk within segment
            asrc    = (w < 8) ? X : X2;
            acol    = seg * 256 + (w & 7) * 32;
            astride = 768;
        } else {
            asrc = X; acol = c * BKW; astride = K3;
        }
        #pragma unroll
        for (int i = tid; i < 512; i += 128) {   // 128 rows x 4 chunks of 16B
            const int r  = i >> 2;
            const int ch = i & 3;
            cpasync16(smem_u32(&As[st][r][ch * 8]),
                      asrc + (size_t)(bm + r) * astride + acol + ch * 8);
            cpasync16(smem_u32(&Bs[st][r][ch * 8]),
                      Wc + (size_t)(bn + r) * K3 + c * BKW + ch * 8);
        }
        asm volatile("cp.async.commit_group;" ::: "memory");
    };

    wmma::fragment<wmma::accumulator, 16, 16, 16, float> acc[4][4];
    #pragma unroll
    for (int i = 0; i < 4; ++i)
        #pragma unroll
        for (int j = 0; j < 4; ++j) wmma::fill_fragment(acc[i][j], 0.0f);

    load_stage(0, 0);

    for (int c = 0; c < NC; ++c) {
        asm volatile("cp.async.wait_group 0;" ::: "memory");
        __syncthreads();                  // stage c&1 ready + visible to all warps
        if (c + 1 < NC) load_stage(c + 1, (c + 1) & 1);  // prefetch overlaps compute
        const int st = c & 1;

        #pragma unroll
        for (int kk = 0; kk < BKW / 16; ++kk) {
            wmma::fragment<wmma::matrix_a, 16, 16, 16, __nv_bfloat16, wmma::row_major> af[4];
            wmma::fragment<wmma::matrix_b, 16, 16, 16, __nv_bfloat16, wmma::col_major> bf[4];
            #pragma unroll
            for (int i = 0; i < 4; ++i)
                wmma::load_matrix_sync(af[i], &As[st][wm + i * 16][kk * 16], LDP);
            #pragma unroll
            for (int j = 0; j < 4; ++j)
                wmma::load_matrix_sync(bf[j], &Bs[st][wn + j * 16][kk * 16], LDP);
            #pragma unroll
            for (int i = 0; i < 4; ++i)
                #pragma unroll
                for (int j = 0; j < 4; ++j)
                    wmma::mma_sync(acc[i][j], af[i], bf[j], acc[i][j]);
        }
    }

    if (!CAT3) {
        #pragma unroll
        for (int i = 0; i < 4; ++i)
            #pragma unroll
            for (int j = 0; j < 4; ++j)
                wmma::store_matrix_sync(
                    &fout[(size_t)(bm + wm + i * 16) * NN + bn + wn + j * 16],
                    acc[i][j], NN, wmma::mem_row_major);
    } else {
        // per-warp 16x16 float staging overlaid on As (mainloop done)
        __syncthreads();
        float* stg = reinterpret_cast<float*>(&As[0][0][0]) + wid * 256;
        const int er = lane >> 1;
        const int ec = (lane & 1) * 8;
        #pragma unroll
        for (int i = 0; i < 4; ++i) {
            #pragma unroll
            for (int j = 0; j < 4; ++j) {
                wmma::store_matrix_sync(stg, acc[i][j], 16, wmma::mem_row_major);
                __syncwarp();
                const int mrow = bm + wm + i * 16 + er;
                const int col  = bn + wn + j * 16 + ec;
                __nv_bfloat16* o = bout + (size_t)mrow * (3 * NN) + col;
                #pragma unroll
                for (int t = 0; t < 8; t += 2) {
                    float v0 = stg[er * 16 + ec + t];
                    float v1 = stg[er * 16 + ec + t + 1];
                    if (ACT == ACT_RELU) {
                        v0 = v0 > 0.f ? v0 : 0.f;
                        v1 = v1 > 0.f ? v1 : 0.f;
                    }
                    __nv_bfloat16 h0, h1, l0, l1;
                    split_bf16(v0, h0, l0); split_bf16(v1, h1, l1);
                    __nv_bfloat162 hh, ll;
                    hh.x = h0; hh.y = h1; ll.x = l0; ll.y = l1;
                    *(__nv_bfloat162*)&o[t]          = hh;   // seg0: hi
                    *(__nv_bfloat162*)&o[NN + t]     = ll;   // seg1: lo
                    *(__nv_bfloat162*)&o[2 * NN + t] = hh;   // seg2: hi
                }
                __syncwarp();
            }
        }
    }
}

// ===== Merged QKV projection: one launch, blockIdx.z selects the GEMM.
// 1536 CTAs = 3.46 waves at 444-CTA capacity -> pays the ragged tail ONCE
// instead of 3x (R14 profile showed 512-CTA launches waste ~46% of a wave).
__global__ void __launch_bounds__(128) k_wqkv() {
    switch (blockIdx.z) {
    case 0:
        wmma_body<ACT_NONE, false, false, 256, 768>(g_xcat, nullptr, g_wqcat, g_qraw, nullptr);
        break;
    case 1:
        wmma_body<ACT_NONE, false, false, 256, 768>(g_scat, nullptr, g_wkcat, g_kraw, nullptr);
        break;
    default:
        wmma_body<ACT_NONE, false, false, 256, 768>(g_scat, nullptr, g_wvcat, g_vproj, nullptr);
        break;
    }
}
__global__ void __launch_bounds__(128) k_wm() {
    wmma_body<ACT_NONE, false, false, 256, 768>(g_mcat, nullptr, g_wmcat, g_msgm, nullptr);
}
__global__ void __launch_bounds__(128) k_w1() {
    // h1cat = cat3(relu([x|msgln] W1^T)); concat composed in the loader
    wmma_body<ACT_RELU, true, true, 512, 1536>(g_xcat, g_mlncat, g_w1cat, nullptr, g_h1cat);
}
__global__ void __launch_bounds__(128) k_w2() {
    wmma_body<ACT_NONE, false, false, 256, 1536>(g_h1cat, nullptr, g_w2cat, g_h2, nullptr);
}

// ===== Weight conversion (ALL 6 matrices in ONE launch; grid.y selects) =====
// Wcat[n, 3K] = [hi | hi | lo]. Output globals bound in device code —
// passing a __device__ global as a host-side arg hits the host shadow symbol
// (ATS swallows the writes silently): the R9/R10 bug. Never do that.
__device__ __forceinline__ void conv_w_elem(const float* __restrict__ W,
                                            __nv_bfloat16* __restrict__ out,
                                            int K, size_t i) {
    const int kh = K >> 1;
    const size_t row = i / kh;
    const int p = (int)(i % kh) * 2;
    const float2 w = *(const float2*)&W[row * K + p];
    __nv_bfloat16 h0, h1, l0, l1;
    split_bf16(w.x, h0, l0); split_bf16(w.y, h1, l1);
    __nv_bfloat162 hh, ll; hh.x = h0; hh.y = h1; ll.x = l0; ll.y = l1;
    __nv_bfloat16* o = out + row * (size_t)(3 * K);
    *(__nv_bfloat162*)&o[p]         = hh;
    *(__nv_bfloat162*)&o[K + p]     = hh;
    *(__nv_bfloat162*)&o[2 * K + p] = ll;
}
__global__ void k_conv_w_all(const float* Wq, const float* Wk, const float* Wv,
                             const float* Wm, const float* W1, const float* W2) {
    const size_t i = (size_t)blockIdx.x * 256 + threadIdx.x;
    switch (blockIdx.y) {
        case 0: if (i < CDIM*CDIM/2) conv_w_elem(Wq, g_wqcat, CDIM, i); break;
        case 1: if (i < CDIM*CDIM/2) conv_w_elem(Wk, g_wkcat, CDIM, i); break;
        case 2: if (i < CDIM*CDIM/2) conv_w_elem(Wv, g_wvcat, CDIM, i); break;
        case 3: if (i < CDIM*CDIM/2) conv_w_elem(Wm, g_wmcat, CDIM, i); break;
        case 4: if (i < HDIM*HDIM/2) conv_w_elem(W1, g_w1cat, HDIM, i); break;
        default: if (i < CDIM*HDIM/2) conv_w_elem(W2, g_w2cat, HDIM, i); break;
    }
}

// x AND source -> cat3 [hi|lo|hi], one launch (grid.y selects)
__global__ void k_conv_xs(const float* __restrict__ X, const float* __restrict__ S) {
    const size_t i = (size_t)blockIdx.x * 256 + threadIdx.x; // over MTOT*128
    const size_t m = i >> 7;
    const int p = (int)(i & 127) * 2;
    const float* in = blockIdx.y ? S : X;
    __nv_bfloat16* o = (blockIdx.y ? g_scat : g_xcat) + m * 768;
    const float2 v = *(const float2*)&in[m * CDIM + p];
    __nv_bfloat16 h0, h1, l0, l1;
    split_bf16(v.x, h0, l0); split_bf16(v.y, h1, l1);
    __nv_bfloat162 hh, ll; hh.x = h0; hh.y = h1; ll.x = l0; ll.y = l1;
    *(__nv_bfloat162*)&o[p]       = hh;
    *(__nv_bfloat162*)&o[256 + p] = ll;
    *(__nv_bfloat162*)&o[512 + p] = hh;
}

// ===== zero KV/Ksum accumulators =====
__global__ void zero_kv_kernel() {
    const int i = blockIdx.x * 256 + threadIdx.x;
    if (i < NB*NHEAD*DHEAD*DHEAD) g_KV[i] = 0.f;
    if (i < NB*NHEAD*DHEAD)       g_Ksum[i] = 0.f;
}

// ===== KV = sum_s elu1(K)[s,h,d] * v[s,h,v] / S ;  Ksum = sum_s elu1(K) =====
__global__ void __launch_bounds__(256) kv_reduce_kernel() {
    const int split = blockIdx.x, h = blockIdx.y, n = blockIdx.z;
    __shared__ __align__(16) float sk[64][32];
    __shared__ __align__(16) float sv[64][32];
    const int tid = threadIdx.x;
    const int v  = tid & 31;
    const int d0 = tid >> 5;

    float kv[4] = {0.f, 0.f, 0.f, 0.f};
    float ks[4] = {0.f, 0.f, 0.f, 0.f};

    const int ROWS = LSEQ / 16;
    const int srow0 = n * LSEQ + split * ROWS;

    for (int s0 = 0; s0 < ROWS; s0 += 64) {
        __syncthreads();
        #pragma unroll
        for (int t = 0; t < 2; ++t) {
            const int i = tid + t * 256;
            const int r = i >> 3, c = (i & 7) * 4;
            const size_t gidx = (size_t)(srow0 + s0 + r) * CDIM + h * DHEAD + c;
            float4 kf = *(const float4*)&g_kraw[gidx];
            kf.x = elu1(kf.x); kf.y = elu1(kf.y);
            kf.z = elu1(kf.z); kf.w = elu1(kf.w);
            *(float4*)&sk[r][c] = kf;
            *(float4*)&sv[r][c] = *(const float4*)&g_vproj[gidx];
        }
        __syncthreads();
        for (int r = 0; r < 64; ++r) {
            const float vv = sv[r][v];
            #pragma unroll
            for (int q = 0; q < 4; ++q) {
                const float kd = sk[r][d0 + 8*q];
                kv[q] += kd * vv;
                ks[q] += kd;
            }
        }
    }
    #pragma unroll
    for (int q = 0; q < 4; ++q) {
        const int d = d0 + 8*q;
        atomicAdd(&g_KV[(((size_t)n*NHEAD + h)*DHEAD + d)*DHEAD + v],
                  kv[q] * (1.0f / (float)LSEQ));
        if (v == 0)
            atomicAdd(&g_Ksum[((size_t)n*NHEAD + h)*DHEAD + d], ks[q]);
    }
}

// ===== attention: Q=elu1(qraw); msg -> cat3 bf16 directly =====
__global__ void __launch_bounds__(256) attn_kernel() {
    const int n = blockIdx.y;
    __shared__ __align__(16) float sKV[NHEAD*DHEAD*DHEAD];
    __shared__ float sKs[NHEAD*DHEAD];
    const int tid = threadIdx.x;

    for (int i = tid; i < NHEAD*DHEAD*DHEAD/4; i += 256)
        *(float4*)&sKV[i*4] = *(const float4*)&g_KV[(size_t)n*NHEAD*DHEAD*DHEAD + i*4];
    sKs[tid] = g_Ksum[n*NHEAD*DHEAD + tid];
    __syncthreads();

    const size_t row = (size_t)n * LSEQ + (size_t)blockIdx.x * 256 + tid;
    const float* qrow = g_qraw + row * CDIM;
    __nv_bfloat16* mr = g_mcat + row * 768;

    for (int h = 0; h < NHEAD; ++h) {
        float Q[DHEAD];
        #pragma unroll
        for (int i = 0; i < 8; ++i)
            *(float4*)&Q[i*4] = *(const float4*)&qrow[h*DHEAD + i*4];
        #pragma unroll
        for (int d = 0; d < DHEAD; ++d) Q[d] = elu1(Q[d]);

        float zden = 1e-6f;
        #pragma unroll
        for (int d = 0; d < DHEAD; ++d) zden += Q[d] * sKs[h*DHEAD + d];
        const float z = (float)LSEQ / zden;

        #pragma unroll
        for (int v4 = 0; v4 < 8; ++v4) {
            float ax = 0.f, ay = 0.f, az = 0.f, aw = 0.f;
            #pragma unroll
            for (int d = 0; d < DHEAD; ++d) {
                const float4 kv = *(const float4*)&sKV[(h*DHEAD + d)*DHEAD + v4*4];
                const float qd = Q[d];
                ax += qd * kv.x; ay += qd * kv.y; az += qd * kv.z; aw += qd * kv.w;
            }
            const float o0 = ax*z, o1 = ay*z, o2 = az*z, o3 = aw*z;
            __nv_bfloat16 h0,h1,h2,h3,l0,l1,l2,l3;
            split_bf16(o0,h0,l0); split_bf16(o1,h1,l1);
            split_bf16(o2,h2,l2); split_bf16(o3,h3,l3);
            __nv_bfloat162 ha,hb,la,lb;
            ha.x=h0; ha.y=h1; hb.x=h2; hb.y=h3;
            la.x=l0; la.y=l1; lb.x=l2; lb.y=l3;
            const int col = h*DHEAD + v4*4;
            *(__nv_bfloat162*)&mr[col]           = ha;
            *(__nv_bfloat162*)&mr[col + 2]       = hb;
            *(__nv_bfloat162*)&mr[256 + col]     = la;
            *(__nv_bfloat162*)&mr[256 + col + 2] = lb;
            *(__nv_bfloat162*)&mr[512 + col]     = ha;
            *(__nv_bfloat162*)&mr[512 + col + 2] = hb;
        }
    }
}

// ===== LN1: LayerNorm(g_msgm) -> g_mlncat [hi|lo|hi] (768-wide) =====
__global__ void __launch_bounds__(256) k_ln1(const float* __restrict__ gamma,
                                             const float* __restrict__ beta) {
    const int w = threadIdx.x >> 5, lane = threadIdx.x & 31;
    const size_t row = (size_t)blockIdx.x * 8 + w;
    const float* p = g_msgm + row * CDIM;

    const float4 v0 = *(const float4*)&p[lane*4];
    const float4 v1 = *(const float4*)&p[128 + lane*4];

    float s  = v0.x + v0.y + v0.z + v0.w + v1.x + v1.y + v1.z + v1.w;
    float s2 = v0.x*v0.x + v0.y*v0.y + v0.z*v0.z + v0.w*v0.w
             + v1.x*v1.x + v1.y*v1.y + v1.z*v1.z + v1.w*v1.w;
    #pragma unroll
    for (int o = 16; o; o >>= 1) {
        s  += __shfl_xor_sync(0xFFFFFFFFu, s,  o);
        s2 += __shfl_xor_sync(0xFFFFFFFFu, s2, o);
    }
    const float mu  = s * (1.f / 256.f);
    const float var = s2 * (1.f / 256.f) - mu * mu;
    const float rs  = rsqrtf(var + 1e-5f);

    __nv_bfloat16* ml = g_mlncat + row * 768;
    #pragma unroll
    for (int half = 0; half < 2; ++half) {
        const float4 v = half ? v1 : v0;
        const int k = half * 128 + lane * 4;
        const float4 gm = *(const float4*)&gamma[k];
        const float4 bt = *(const float4*)&beta[k];
        const float o0 = (v.x - mu)*rs*gm.x + bt.x;
        const float o1 = (v.y - mu)*rs*gm.y + bt.y;
        const float o2 = (v.z - mu)*rs*gm.z + bt.z;
        const float o3 = (v.w - mu)*rs*gm.w + bt.w;
        __nv_bfloat16 h0,h1,h2,h3,l0,l1,l2,l3;
        split_bf16(o0,h0,l0); split_bf16(o1,h1,l1);
        split_bf16(o2,h2,l2); split_bf16(o3,h3,l3);
        __nv_bfloat162 ha,hb,la,lb;
        ha.x=h0; ha.y=h1; hb.x=h2; hb.y=h3;
        la.x=l0; la.y=l1; lb.x=l2; lb.y=l3;
        *(__nv_bfloat162*)&ml[k]            = ha;
        *(__nv_bfloat162*)&ml[k + 2]        = hb;
        *(__nv_bfloat162*)&ml[256 + k]      = la;
        *(__nv_bfloat162*)&ml[256 + k + 2]  = lb;
        *(__nv_bfloat162*)&ml[512 + k]      = ha;
        *(__nv_bfloat162*)&ml[512 + k + 2]  = hb;
    }
}

// ===== LN2 + residual: out = x + LN(g_h2) =====
__global__ void __launch_bounds__(256) k_ln2(const float* __restrict__ gamma,
                                             const float* __restrict__ beta,
                                             const float* __restrict__ xres,
                                             float* __restrict__ out) {
    const int w = threadIdx.x >> 5, lane = threadIdx.x & 31;
    const size_t row = (size_t)blockIdx.x * 8 + w;
    const float* p = g_h2 + row * CDIM;

    const float4 v0 = *(const float4*)&p[lane*4];
    const float4 v1 = *(const float4*)&p[128 + lane*4];

    float s  = v0.x + v0.y + v0.z + v0.w + v1.x + v1.y + v1.z + v1.w;
    float s2 = v0.x*v0.x + v0.y*v0.y + v0.z*v0.z + v0.w*v0.w
             + v1.x*v1.x + v1.y*v1.y + v1.z*v1.z + v1.w*v1.w;
    #pragma unroll
    for (int o = 16; o; o >>= 1) {
        s  += __shfl_xor_sync(0xFFFFFFFFu, s,  o);
        s2 += __shfl_xor_sync(0xFFFFFFFFu, s2, o);
    }
    const float mu  = s * (1.f / 256.f);
    const float var = s2 * (1.f / 256.f) - mu * mu;
    const float rs  = rsqrtf(var + 1e-5f);

    const float4 gm0 = *(const float4*)&gamma[lane*4];
    const float4 gm1 = *(const float4*)&gamma[128 + lane*4];
    const float4 bt0 = *(const float4*)&beta[lane*4];
    const float4 bt1 = *(const float4*)&beta[128 + lane*4];
    const float4 x0  = *(const float4*)&xres[row*CDIM + lane*4];
    const float4 x1  = *(const float4*)&xres[row*CDIM + 128 + lane*4];

    float4 o0, o1;
    o0.x = x0.x + (v0.x - mu)*rs*gm0.x + bt0.x;  o0.y = x0.y + (v0.y - mu)*rs*gm0.y + bt0.y;
    o0.z = x0.z + (v0.z - mu)*rs*gm0.z + bt0.z;  o0.w = x0.w + (v0.w - mu)*rs*gm0.w + bt0.w;
    o1.x = x1.x + (v1.x - mu)*rs*gm1.x + bt1.x;  o1.y = x1.y + (v1.y - mu)*rs*gm1.y + bt1.y;
    o1.z = x1.z + (v1.z - mu)*rs*gm1.z + bt1.z;  o1.w = x1.w + (v1.w - mu)*rs*gm1.w + bt1.w;

    *(float4*)&out[row*CDIM + lane*4]       = o0;
    *(float4*)&out[row*CDIM + 128 + lane*4] = o1;
}

// ===== Launch =====
extern "C" void kernel_launch(void* const* d_in, const int* in_sizes, int n_in,
                              void* d_out, int out_size) {
    const float* x    = (const float*)d_in[0];
    const float* src  = (const float*)d_in[1];
    const float* Wq   = (const float*)d_in[2];
    const float* Wk   = (const float*)d_in[3];
    const float* Wv   = (const float*)d_in[4];
    const float* Wm   = (const float*)d_in[5];
    const float* ln1g = (const float*)d_in[6];
    const float* ln1b = (const float*)d_in[7];
    const float* W1   = (const float*)d_in[8];
    const float* W2   = (const float*)d_in[9];
    const float* ln2g = (const float*)d_in[10];
    const float* ln2b = (const float*)d_in[11];
    float* out = (float*)d_out;

    const dim3 blk(128);
    const dim3 gqkv(256 / 128, MTOT / 128, 3);  // (2, 256, 3) merged QKV
    const dim3 gq(256 / 128, MTOT / 128);       // (2, 256)
    const dim3 g1(512 / 128, MTOT / 128);       // (4, 256)

    k_conv_w_all<<<dim3(512, 6), 256>>>(Wq, Wk, Wv, Wm, W1, W2);      // 1
    k_conv_xs<<<dim3((size_t)MTOT*128/256, 2), 256>>>(x, src);        // 2
    zero_kv_kernel<<<128, 256>>>();                                   // 3
    k_wqkv<<<gqkv, blk>>>();                                          // 4 <- profiled
    kv_reduce_kernel<<<dim3(16, NHEAD, NB), 256>>>();   // elu applied on K here
    attn_kernel<<<dim3(LSEQ / 256, NB), 256>>>();       // elu on Q; msg -> g_mcat
    k_wm<<<gq, blk>>>();                    // msgm = msg Wm^T
    k_ln1<<<MTOT / 8, 256>>>(ln1g, ln1b);   // msg_ln -> g_mlncat (cat3)
    k_w1<<<g1, blk>>>();                    // h1cat = cat3(relu([x|msgln] W1^T))
    k_w2<<<gq, blk>>>();                    // h2 = relu(h1) W2^T
    k_ln2<<<MTOT / 8, 256>>>(ln2g, ln2b, x, out);
}

// round 17
// speedup vs baseline: 1.0496x; 1.0124x over previous
#include <cuda_runtime.h>
#include <cuda_bf16.h>
#include <mma.h>
#include <math.h>
#include <stdint.h>

using namespace nvcuda;

// ===== Problem constants (fixed shapes) =====
#define NB    4
#define LSEQ  8192
#define MTOT  (NB*LSEQ)   // 32768 rows
#define CDIM  256
#define HDIM  512
#define NHEAD 8
#define DHEAD 32

// ===== Scratch (no cudaMalloc; __device__ globals) =====
__device__ __align__(128) float g_qraw [(size_t)MTOT*CDIM]; // x@Wq^T (pre-ELU)
__device__ __align__(128) float g_kraw [(size_t)MTOT*CDIM]; // src@Wk^T (pre-ELU)
__device__ __align__(128) float g_vproj[(size_t)MTOT*CDIM];
__device__ __align__(128) float g_msgm [(size_t)MTOT*CDIM];
__device__ __align__(128) float g_h2   [(size_t)MTOT*CDIM];
__device__ float g_KV  [NB*NHEAD*DHEAD*DHEAD]; // includes 1/S
__device__ float g_Ksum[NB*NHEAD*DHEAD];
// bf16 split-2 "cat3" operands: X-side = [hi | lo | hi], W-side = [hi | hi | lo]
// single GEMM over 3K computes hi*hi + lo*hi + hi*lo  (only lo*lo ~2^-16 dropped)
__device__ __align__(128) __nv_bfloat16 g_xcat  [(size_t)MTOT*3*CDIM]; // x       [M,768]
__device__ __align__(128) __nv_bfloat16 g_scat  [(size_t)MTOT*3*CDIM]; // source  [M,768]
__device__ __align__(128) __nv_bfloat16 g_mcat  [(size_t)MTOT*3*CDIM]; // message [M,768]
__device__ __align__(128) __nv_bfloat16 g_mlncat[(size_t)MTOT*3*CDIM]; // LN1 msg [M,768]
__device__ __align__(128) __nv_bfloat16 g_h1cat [(size_t)MTOT*3*HDIM]; // relu h1 [M,1536]
__device__ __align__(128) __nv_bfloat16 g_wqcat[(size_t)CDIM*3*CDIM];
__device__ __align__(128) __nv_bfloat16 g_wkcat[(size_t)CDIM*3*CDIM];
__device__ __align__(128) __nv_bfloat16 g_wvcat[(size_t)CDIM*3*CDIM];
__device__ __align__(128) __nv_bfloat16 g_wmcat[(size_t)CDIM*3*CDIM];
__device__ __align__(128) __nv_bfloat16 g_w1cat[(size_t)HDIM*3*HDIM];
__device__ __align__(128) __nv_bfloat16 g_w2cat[(size_t)CDIM*3*HDIM];

__device__ __forceinline__ float elu1(float v) {
    return v > 0.f ? v + 1.f : expf(v); // elu(v)+1
}

// ===== helpers =====
__device__ __forceinline__ uint32_t smem_u32(const void* p) {
    uint32_t a;
    asm("{ .reg .u64 t; cvta.to.shared.u64 t, %1; cvt.u32.u64 %0, t; }" : "=r"(a) : "l"(p));
    return a;
}
__device__ __forceinline__ void cpasync16(uint32_t s, const void* g) {
    asm volatile("cp.async.cg.shared.global [%0], [%1], 16;" :: "r"(s), "l"(g) : "memory");
}
// bf16 hi/lo split
__device__ __forceinline__ void split_bf16(float v, __nv_bfloat16& h, __nv_bfloat16& l) {
    h = __float2bfloat16(v);
    l = __float2bfloat16(v - __bfloat162float(h));
}

// ===== WMMA GEMM:  Y[M,NN] = A[M,K3] @ Wcat[NN,K3]^T =====
// CTA 128x128, 128 threads, 4 warps (2x2), warp tile 64x64 (best mma:ldsm = 2.0;
// R12: 8-warp/64x32 raises LDSM 1.5x and regresses).
// 2-stage static-48KB cp.async ring (R14: 3-stage neutral — regs cap occupancy).
// R15 lesson: merging 3 template instantiations under one switch made ptxas
// allocate the UNION (222 regs, occ 2 CTAs/SM). Fix: runtime pointer select
// into ONE instantiation (regs ~166 -> 3 CTAs/SM = 444-CTA capacity).
// [R16 bench was lost to a container-infra failure; this is the same change
//  re-benched on a fresh hold — single-variable attribution preserved.]
// SPLIT: A composed on the fly from two 768-wide sources ([x|msg_ln] never
// materialized). CAT3 epilogue: act + hi/lo split -> [hi|lo|hi].
#define BKW 32
#define LDP 40   // BKW + 8 pad; 80B rows, multiple of 16B

#define ACT_NONE 0
#define ACT_RELU 2

template<int ACT, bool CAT3, bool SPLIT, int NN, int K3>
__device__ __forceinline__ void wmma_body(const __nv_bfloat16* __restrict__ X,
                                          const __nv_bfloat16* __restrict__ X2,
                                          const __nv_bfloat16* __restrict__ Wc,
                                          float* __restrict__ fout,
                                          __nv_bfloat16* __restrict__ bout) {
    __shared__ __align__(128) __nv_bfloat16 As[2][128][LDP]; // 2*10240B
    __shared__ __align__(128) __nv_bfloat16 Bs[2][128][LDP];

    const int tid  = threadIdx.x;     // 0..127
    const int wid  = tid >> 5;        // 0..3
    const int lane = tid & 31;
    const int bm   = blockIdx.y * 128;
    const int bn   = blockIdx.x * 128;
    const int wm   = (wid & 1) * 64;  // warp grid 2x2, tile 64x64
    const int wn   = (wid >> 1) * 64;
    constexpr int NC = K3 / BKW;

    auto load_stage = [&](int c, int st) {
        const __nv_bfloat16* asrc;
        int acol, astride;
        if (SPLIT) {                          // virtual [x | msg_ln] concat
            const int seg = c >> 4;           // 512-col segment
            const int w   = c & 15;           // chunk within segment
            asrc    = (w < 8) ? X : X2;
            acol    = seg * 256 + (w & 7) * 32;
            astride = 768;
        } else {
            asrc = X; acol = c * BKW; astride = K3;
        }
        #pragma unroll
        for (int i = tid; i < 512; i += 128) {   // 128 rows x 4 chunks of 16B
            const int r  = i >> 2;
            const int ch = i & 3;
            cpasync16(smem_u32(&As[st][r][ch * 8]),
                      asrc + (size_t)(bm + r) * astride + acol + ch * 8);
            cpasync16(smem_u32(&Bs[st][r][ch * 8]),
                      Wc + (size_t)(bn + r) * K3 + c * BKW + ch * 8);
        }
        asm volatile("cp.async.commit_group;" ::: "memory");
    };

    wmma::fragment<wmma::accumulator, 16, 16, 16, float> acc[4][4];
    #pragma unroll
    for (int i = 0; i < 4; ++i)
        #pragma unroll
        for (int j = 0; j < 4; ++j) wmma::fill_fragment(acc[i][j], 0.0f);

    load_stage(0, 0);

    for (int c = 0; c < NC; ++c) {
        asm volatile("cp.async.wait_group 0;" ::: "memory");
        __syncthreads();                  // stage c&1 ready + visible to all warps
        if (c + 1 < NC) load_stage(c + 1, (c + 1) & 1);  // prefetch overlaps compute
        const int st = c & 1;

        #pragma unroll
        for (int kk = 0; kk < BKW / 16; ++kk) {
            wmma::fragment<wmma::matrix_a, 16, 16, 16, __nv_bfloat16, wmma::row_major> af[4];
            wmma::fragment<wmma::matrix_b, 16, 16, 16, __nv_bfloat16, wmma::col_major> bf[4];
            #pragma unroll
            for (int i = 0; i < 4; ++i)
                wmma::load_matrix_sync(af[i], &As[st][wm + i * 16][kk * 16], LDP);
            #pragma unroll
            for (int j = 0; j < 4; ++j)
                wmma::load_matrix_sync(bf[j], &Bs[st][wn + j * 16][kk * 16], LDP);
            #pragma unroll
            for (int i = 0; i < 4; ++i)
                #pragma unroll
                for (int j = 0; j < 4; ++j)
                    wmma::mma_sync(acc[i][j], af[i], bf[j], acc[i][j]);
        }
    }

    if (!CAT3) {
        #pragma unroll
        for (int i = 0; i < 4; ++i)
            #pragma unroll
            for (int j = 0; j < 4; ++j)
                wmma::store_matrix_sync(
                    &fout[(size_t)(bm + wm + i * 16) * NN + bn + wn + j * 16],
                    acc[i][j], NN, wmma::mem_row_major);
    } else {
        // per-warp 16x16 float staging overlaid on As (mainloop done)
        __syncthreads();
        float* stg = reinterpret_cast<float*>(&As[0][0][0]) + wid * 256;
        const int er = lane >> 1;
        const int ec = (lane & 1) * 8;
        #pragma unroll
        for (int i = 0; i < 4; ++i) {
            #pragma unroll
            for (int j = 0; j < 4; ++j) {
                wmma::store_matrix_sync(stg, acc[i][j], 16, wmma::mem_row_major);
                __syncwarp();
                const int mrow = bm + wm + i * 16 + er;
                const int col  = bn + wn + j * 16 + ec;
                __nv_bfloat16* o = bout + (size_t)mrow * (3 * NN) + col;
                #pragma unroll
                for (int t = 0; t < 8; t += 2) {
                    float v0 = stg[er * 16 + ec + t];
                    float v1 = stg[er * 16 + ec + t + 1];
                    if (ACT == ACT_RELU) {
                        v0 = v0 > 0.f ? v0 : 0.f;
                        v1 = v1 > 0.f ? v1 : 0.f;
                    }
                    __nv_bfloat16 h0, h1, l0, l1;
                    split_bf16(v0, h0, l0); split_bf16(v1, h1, l1);
                    __nv_bfloat162 hh, ll;
                    hh.x = h0; hh.y = h1; ll.x = l0; ll.y = l1;
                    *(__nv_bfloat162*)&o[t]          = hh;   // seg0: hi
                    *(__nv_bfloat162*)&o[NN + t]     = ll;   // seg1: lo
                    *(__nv_bfloat162*)&o[2 * NN + t] = hh;   // seg2: hi
                }
                __syncwarp();
            }
        }
    }
}

// ===== Merged QKV projection: one launch, blockIdx.z selects SOURCES at
// runtime, then calls a SINGLE template instantiation (one codegen body,
// regs ~166 -> 3 CTAs/SM; R15's per-case instantiation hit 222 regs / 2 CTAs).
__global__ void __launch_bounds__(128) k_wqkv() {
    const __nv_bfloat16* Xp;
    const __nv_bfloat16* Wp;
    float* Yp;
    if (blockIdx.z == 0)      { Xp = g_xcat; Wp = g_wqcat; Yp = g_qraw; }
    else if (blockIdx.z == 1) { Xp = g_scat; Wp = g_wkcat; Yp = g_kraw; }
    else                      { Xp = g_scat; Wp = g_wvcat; Yp = g_vproj; }
    wmma_body<ACT_NONE, false, false, 256, 768>(Xp, nullptr, Wp, Yp, nullptr);
}
__global__ void __launch_bounds__(128) k_wm() {
    wmma_body<ACT_NONE, false, false, 256, 768>(g_mcat, nullptr, g_wmcat, g_msgm, nullptr);
}
__global__ void __launch_bounds__(128) k_w1() {
    // h1cat = cat3(relu([x|msgln] W1^T)); concat composed in the loader
    wmma_body<ACT_RELU, true, true, 512, 1536>(g_xcat, g_mlncat, g_w1cat, nullptr, g_h1cat);
}
__global__ void __launch_bounds__(128) k_w2() {
    wmma_body<ACT_NONE, false, false, 256, 1536>(g_h1cat, nullptr, g_w2cat, g_h2, nullptr);
}

// ===== Weight conversion (ALL 6 matrices in ONE launch; grid.y selects) =====
// Wcat[n, 3K] = [hi | hi | lo]. Output globals bound in device code —
// passing a __device__ global as a host-side arg hits the host shadow symbol
// (ATS swallows the writes silently): the R9/R10 bug. Never do that.
__device__ __forceinline__ void conv_w_elem(const float* __restrict__ W,
                                            __nv_bfloat16* __restrict__ out,
                                            int K, size_t i) {
    const int kh = K >> 1;
    const size_t row = i / kh;
    const int p = (int)(i % kh) * 2;
    const float2 w = *(const float2*)&W[row * K + p];
    __nv_bfloat16 h0, h1, l0, l1;
    split_bf16(w.x, h0, l0); split_bf16(w.y, h1, l1);
    __nv_bfloat162 hh, ll; hh.x = h0; hh.y = h1; ll.x = l0; ll.y = l1;
    __nv_bfloat16* o = out + row * (size_t)(3 * K);
    *(__nv_bfloat162*)&o[p]         = hh;
    *(__nv_bfloat162*)&o[K + p]     = hh;
    *(__nv_bfloat162*)&o[2 * K + p] = ll;
}
__global__ void k_conv_w_all(const float* Wq, const float* Wk, const float* Wv,
                             const float* Wm, const float* W1, const float* W2) {
    const size_t i = (size_t)blockIdx.x * 256 + threadIdx.x;
    switch (blockIdx.y) {
        case 0: if (i < CDIM*CDIM/2) conv_w_elem(Wq, g_wqcat, CDIM, i); break;
        case 1: if (i < CDIM*CDIM/2) conv_w_elem(Wk, g_wkcat, CDIM, i); break;
        case 2: if (i < CDIM*CDIM/2) conv_w_elem(Wv, g_wvcat, CDIM, i); break;
        case 3: if (i < CDIM*CDIM/2) conv_w_elem(Wm, g_wmcat, CDIM, i); break;
        case 4: if (i < HDIM*HDIM/2) conv_w_elem(W1, g_w1cat, HDIM, i); break;
        default: if (i < CDIM*HDIM/2) conv_w_elem(W2, g_w2cat, HDIM, i); break;
    }
}

// x AND source -> cat3 [hi|lo|hi], one launch (grid.y selects)
__global__ void k_conv_xs(const float* __restrict__ X, const float* __restrict__ S) {
    const size_t i = (size_t)blockIdx.x * 256 + threadIdx.x; // over MTOT*128
    const size_t m = i >> 7;
    const int p = (int)(i & 127) * 2;
    const float* in = blockIdx.y ? S : X;
    __nv_bfloat16* o = (blockIdx.y ? g_scat : g_xcat) + m * 768;
    const float2 v = *(const float2*)&in[m * CDIM + p];
    __nv_bfloat16 h0, h1, l0, l1;
    split_bf16(v.x, h0, l0); split_bf16(v.y, h1, l1);
    __nv_bfloat162 hh, ll; hh.x = h0; hh.y = h1; ll.x = l0; ll.y = l1;
    *(__nv_bfloat162*)&o[p]       = hh;
    *(__nv_bfloat162*)&o[256 + p] = ll;
    *(__nv_bfloat162*)&o[512 + p] = hh;
}

// ===== zero KV/Ksum accumulators =====
__global__ void zero_kv_kernel() {
    const int i = blockIdx.x * 256 + threadIdx.x;
    if (i < NB*NHEAD*DHEAD*DHEAD) g_KV[i] = 0.f;
    if (i < NB*NHEAD*DHEAD)       g_Ksum[i] = 0.f;
}

// ===== KV = sum_s elu1(K)[s,h,d] * v[s,h,v] / S ;  Ksum = sum_s elu1(K) =====
__global__ void __launch_bounds__(256) kv_reduce_kernel() {
    const int split = blockIdx.x, h = blockIdx.y, n = blockIdx.z;
    __shared__ __align__(16) float sk[64][32];
    __shared__ __align__(16) float sv[64][32];
    const int tid = threadIdx.x;
    const int v  = tid & 31;
    const int d0 = tid >> 5;

    float kv[4] = {0.f, 0.f, 0.f, 0.f};
    float ks[4] = {0.f, 0.f, 0.f, 0.f};

    const int ROWS = LSEQ / 16;
    const int srow0 = n * LSEQ + split * ROWS;

    for (int s0 = 0; s0 < ROWS; s0 += 64) {
        __syncthreads();
        #pragma unroll
        for (int t = 0; t < 2; ++t) {
            const int i = tid + t * 256;
            const int r = i >> 3, c = (i & 7) * 4;
            const size_t gidx = (size_t)(srow0 + s0 + r) * CDIM + h * DHEAD + c;
            float4 kf = *(const float4*)&g_kraw[gidx];
            kf.x = elu1(kf.x); kf.y = elu1(kf.y);
            kf.z = elu1(kf.z); kf.w = elu1(kf.w);
            *(float4*)&sk[r][c] = kf;
            *(float4*)&sv[r][c] = *(const float4*)&g_vproj[gidx];
        }
        __syncthreads();
        for (int r = 0; r < 64; ++r) {
            const float vv = sv[r][v];
            #pragma unroll
            for (int q = 0; q < 4; ++q) {
                const float kd = sk[r][d0 + 8*q];
                kv[q] += kd * vv;
                ks[q] += kd;
            }
        }
    }
    #pragma unroll
    for (int q = 0; q < 4; ++q) {
        const int d = d0 + 8*q;
        atomicAdd(&g_KV[(((size_t)n*NHEAD + h)*DHEAD + d)*DHEAD + v],
                  kv[q] * (1.0f / (float)LSEQ));
        if (v == 0)
            atomicAdd(&g_Ksum[((size_t)n*NHEAD + h)*DHEAD + d], ks[q]);
    }
}

// ===== attention: Q=elu1(qraw); msg -> cat3 bf16 directly =====
__global__ void __launch_bounds__(256) attn_kernel() {
    const int n = blockIdx.y;
    __shared__ __align__(16) float sKV[NHEAD*DHEAD*DHEAD];
    __shared__ float sKs[NHEAD*DHEAD];
    const int tid = threadIdx.x;

    for (int i = tid; i < NHEAD*DHEAD*DHEAD/4; i += 256)
        *(float4*)&sKV[i*4] = *(const float4*)&g_KV[(size_t)n*NHEAD*DHEAD*DHEAD + i*4];
    sKs[tid] = g_Ksum[n*NHEAD*DHEAD + tid];
    __syncthreads();

    const size_t row = (size_t)n * LSEQ + (size_t)blockIdx.x * 256 + tid;
    const float* qrow = g_qraw + row * CDIM;
    __nv_bfloat16* mr = g_mcat + row * 768;

    for (int h = 0; h < NHEAD; ++h) {
        float Q[DHEAD];
        #pragma unroll
        for (int i = 0; i < 8; ++i)
            *(float4*)&Q[i*4] = *(const float4*)&qrow[h*DHEAD + i*4];
        #pragma unroll
        for (int d = 0; d < DHEAD; ++d) Q[d] = elu1(Q[d]);

        float zden = 1e-6f;
        #pragma unroll
        for (int d = 0; d < DHEAD; ++d) zden += Q[d] * sKs[h*DHEAD + d];
        const float z = (float)LSEQ / zden;

        #pragma unroll
        for (int v4 = 0; v4 < 8; ++v4) {
            float ax = 0.f, ay = 0.f, az = 0.f, aw = 0.f;
            #pragma unroll
            for (int d = 0; d < DHEAD; ++d) {
                const float4 kv = *(const float4*)&sKV[(h*DHEAD + d)*DHEAD + v4*4];
                const float qd = Q[d];
                ax += qd * kv.x; ay += qd * kv.y; az += qd * kv.z; aw += qd * kv.w;
            }
            const float o0 = ax*z, o1 = ay*z, o2 = az*z, o3 = aw*z;
            __nv_bfloat16 h0,h1,h2,h3,l0,l1,l2,l3;
            split_bf16(o0,h0,l0); split_bf16(o1,h1,l1);
            split_bf16(o2,h2,l2); split_bf16(o3,h3,l3);
            __nv_bfloat162 ha,hb,la,lb;
            ha.x=h0; ha.y=h1; hb.x=h2; hb.y=h3;
            la.x=l0; la.y=l1; lb.x=l2; lb.y=l3;
            const int col = h*DHEAD + v4*4;
            *(__nv_bfloat162*)&mr[col]           = ha;
            *(__nv_bfloat162*)&mr[col + 2]       = hb;
            *(__nv_bfloat162*)&mr[256 + col]     = la;
            *(__nv_bfloat162*)&mr[256 + col + 2] = lb;
            *(__nv_bfloat162*)&mr[512 + col]     = ha;
            *(__nv_bfloat162*)&mr[512 + col + 2] = hb;
        }
    }
}

// ===== LN1: LayerNorm(g_msgm) -> g_mlncat [hi|lo|hi] (768-wide) =====
__global__ void __launch_bounds__(256) k_ln1(const float* __restrict__ gamma,
                                             const float* __restrict__ beta) {
    const int w = threadIdx.x >> 5, lane = threadIdx.x & 31;
    const size_t row = (size_t)blockIdx.x * 8 + w;
    const float* p = g_msgm + row * CDIM;

    const float4 v0 = *(const float4*)&p[lane*4];
    const float4 v1 = *(const float4*)&p[128 + lane*4];

    float s  = v0.x + v0.y + v0.z + v0.w + v1.x + v1.y + v1.z + v1.w;
    float s2 = v0.x*v0.x + v0.y*v0.y + v0.z*v0.z + v0.w*v0.w
             + v1.x*v1.x + v1.y*v1.y + v1.z*v1.z + v1.w*v1.w;
    #pragma unroll
    for (int o = 16; o; o >>= 1) {
        s  += __shfl_xor_sync(0xFFFFFFFFu, s,  o);
        s2 += __shfl_xor_sync(0xFFFFFFFFu, s2, o);
    }
    const float mu  = s * (1.f / 256.f);
    const float var = s2 * (1.f / 256.f) - mu * mu;
    const float rs  = rsqrtf(var + 1e-5f);

    __nv_bfloat16* ml = g_mlncat + row * 768;
    #pragma unroll
    for (int half = 0; half < 2; ++half) {
        const float4 v = half ? v1 : v0;
        const int k = half * 128 + lane * 4;
        const float4 gm = *(const float4*)&gamma[k];
        const float4 bt = *(const float4*)&beta[k];
        const float o0 = (v.x - mu)*rs*gm.x + bt.x;
        const float o1 = (v.y - mu)*rs*gm.y + bt.y;
        const float o2 = (v.z - mu)*rs*gm.z + bt.z;
        const float o3 = (v.w - mu)*rs*gm.w + bt.w;
        __nv_bfloat16 h0,h1,h2,h3,l0,l1,l2,l3;
        split_bf16(o0,h0,l0); split_bf16(o1,h1,l1);
        split_bf16(o2,h2,l2); split_bf16(o3,h3,l3);
        __nv_bfloat162 ha,hb,la,lb;
        ha.x=h0; ha.y=h1; hb.x=h2; hb.y=h3;
        la.x=l0; la.y=l1; lb.x=l2; lb.y=l3;
        *(__nv_bfloat162*)&ml[k]            = ha;
        *(__nv_bfloat162*)&ml[k + 2]        = hb;
        *(__nv_bfloat162*)&ml[256 + k]      = la;
        *(__nv_bfloat162*)&ml[256 + k + 2]  = lb;
        *(__nv_bfloat162*)&ml[512 + k]      = ha;
        *(__nv_bfloat162*)&ml[512 + k + 2]  = hb;
    }
}

// ===== LN2 + residual: out = x + LN(g_h2) =====
__global__ void __launch_bounds__(256) k_ln2(const float* __restrict__ gamma,
                                             const float* __restrict__ beta,
                                             const float* __restrict__ xres,
                                             float* __restrict__ out) {
    const int w = threadIdx.x >> 5, lane = threadIdx.x & 31;
    const size_t row = (size_t)blockIdx.x * 8 + w;
    const float* p = g_h2 + row * CDIM;

    const float4 v0 = *(const float4*)&p[lane*4];
    const float4 v1 = *(const float4*)&p[128 + lane*4];

    float s  = v0.x + v0.y + v0.z + v0.w + v1.x + v1.y + v1.z + v1.w;
    float s2 = v0.x*v0.x + v0.y*v0.y + v0.z*v0.z + v0.w*v0.w
             + v1.x*v1.x + v1.y*v1.y + v1.z*v1.z + v1.w*v1.w;
    #pragma unroll
    for (int o = 16; o; o >>= 1) {
        s  += __shfl_xor_sync(0xFFFFFFFFu, s,  o);
        s2 += __shfl_xor_sync(0xFFFFFFFFu, s2, o);
    }
    const float mu  = s * (1.f / 256.f);
    const float var = s2 * (1.f / 256.f) - mu * mu;
    const float rs  = rsqrtf(var + 1e-5f);

    const float4 gm0 = *(const float4*)&gamma[lane*4];
    const float4 gm1 = *(const float4*)&gamma[128 + lane*4];
    const float4 bt0 = *(const float4*)&beta[lane*4];
    const float4 bt1 = *(const float4*)&beta[128 + lane*4];
    const float4 x0  = *(const float4*)&xres[row*CDIM + lane*4];
    const float4 x1  = *(const float4*)&xres[row*CDIM + 128 + lane*4];

    float4 o0, o1;
    o0.x = x0.x + (v0.x - mu)*rs*gm0.x + bt0.x;  o0.y = x0.y + (v0.y - mu)*rs*gm0.y + bt0.y;
    o0.z = x0.z + (v0.z - mu)*rs*gm0.z + bt0.z;  o0.w = x0.w + (v0.w - mu)*rs*gm0.w + bt0.w;
    o1.x = x1.x + (v1.x - mu)*rs*gm1.x + bt1.x;  o1.y = x1.y + (v1.y - mu)*rs*gm1.y + bt1.y;
    o1.z = x1.z + (v1.z - mu)*rs*gm1.z + bt1.z;  o1.w = x1.w + (v1.w - mu)*rs*gm1.w + bt1.w;

    *(float4*)&out[row*CDIM + lane*4]       = o0;
    *(float4*)&out[row*CDIM + 128 + lane*4] = o1;
}

// ===== Launch =====
extern "C" void kernel_launch(void* const* d_in, const int* in_sizes, int n_in,
                              void* d_out, int out_size) {
    const float* x    = (const float*)d_in[0];
    const float* src  = (const float*)d_in[1];
    const float* Wq   = (const float*)d_in[2];
    const float* Wk   = (const float*)d_in[3];
    const float* Wv   = (const float*)d_in[4];
    const float* Wm   = (const float*)d_in[5];
    const float* ln1g = (const float*)d_in[6];
    const float* ln1b = (const float*)d_in[7];
    const float* W1   = (const float*)d_in[8];
    const float* W2   = (const float*)d_in[9];
    const float* ln2g = (const float*)d_in[10];
    const float* ln2b = (const float*)d_in[11];
    float* out = (float*)d_out;

    const dim3 blk(128);
    const dim3 gqkv(256 / 128, MTOT / 128, 3);  // (2, 256, 3) merged QKV
    const dim3 gq(256 / 128, MTOT / 128);       // (2, 256)
    const dim3 g1(512 / 128, MTOT / 128);       // (4, 256)

    k_conv_w_all<<<dim3(512, 6), 256>>>(Wq, Wk, Wv, Wm, W1, W2);      // 1
    k_conv_xs<<<dim3((size_t)MTOT*128/256, 2), 256>>>(x, src);        // 2
    zero_kv_kernel<<<128, 256>>>();                                   // 3
    k_wqkv<<<gqkv, blk>>>();                                          // 4 <- profiled
    kv_reduce_kernel<<<dim3(16, NHEAD, NB), 256>>>();   // elu applied on K here
    attn_kernel<<<dim3(LSEQ / 256, NB), 256>>>();       // elu on Q; msg -> g_mcat
    k_wm<<<gq, blk>>>();                    // msgm = msg Wm^T
    k_ln1<<<MTOT / 8, 256>>>(ln1g, ln1b);   // msg_ln -> g_mlncat (cat3)
    k_w1<<<g1, blk>>>();                    // h1cat = cat3(relu([x|msgln] W1^T))
    k_w2<<<gq, blk>>>();                    // h2 = relu(h1) W2^T
    k_ln2<<<MTOT / 8, 256>>>(ln2g, ln2b, x, out);
}